// round 8
// baseline (speedup 1.0000x reference)
#include <cuda_runtime.h>
#include <stdint.h>

#define NUM_NODES 100000
#define NUM_EDGES 400000
#define NRND      48          // counter slots (rounds never exceed ~17)
#define LOCAL_N   8192        // handoff threshold to single-block mode
#define BLOCKS    148
#define TPB       1024
#define NT        (BLOCKS * TPB)

typedef unsigned long long u64;

// Scratch (__device__ globals; zero-initialized at load; no allocs allowed).
// Cross-replay invariant: g_best == 0 and g_cnt == 0 at kernel entry
// (guaranteed by the end-of-replay clear protocol below).
__device__ u64      g_key[NUM_EDGES];     // 51-bit order key: score32<<19 | (524287-e)
__device__ int      g_label[NUM_NODES];
__device__ u64      g_best[NUM_NODES];    // tagged: (round+1)<<51 | key51
__device__ u64      g_wl[2][NUM_EDGES];   // packed: e<<34 | ra<<17 | rb
__device__ int      g_cnt[NRND];
__device__ unsigned g_count = 0;          // barrier arrivals
__device__ unsigned g_gen   = 0;          // barrier generation (wrap-safe across replays)

// ---- software grid barrier (validated: rel_err 0.0 in R2/R3) ----
__device__ __forceinline__ unsigned ld_acq(const unsigned* p) {
    unsigned v;
    asm volatile("ld.acquire.gpu.u32 %0, [%1];" : "=r"(v) : "l"(p) : "memory");
    return v;
}
__device__ __forceinline__ void st_rel(unsigned* p, unsigned v) {
    asm volatile("st.release.gpu.u32 [%0], %1;" :: "l"(p), "r"(v) : "memory");
}
__device__ __forceinline__ void gbar() {
    __syncthreads();
    if (threadIdx.x == 0) {
        unsigned my = ld_acq(&g_gen);
        __threadfence();
        unsigned a = atomicAdd(&g_count, 1u);
        if (a == BLOCKS - 1) {
            g_count = 0;
            __threadfence();
            st_rel(&g_gen, my + 1u);
        } else {
            while (ld_acq(&g_gen) == my) __nanosleep(20);
        }
    }
    __syncthreads();
}

// find with FULL path compression (phase A only; no concurrent hooks, so the
// root is stable and all compression writes jump strictly toward the root)
__device__ __forceinline__ int find_c(int v) {
    int r = g_label[v];
    if (r == v) return v;
    int p = g_label[r];
    while (p != r) { r = p; p = g_label[r]; }
    while (v != r) { int nx = g_label[v]; g_label[v] = r; v = nx; }
    return r;
}

// ---- phase A (rounds >= 1): find roots, per-component max via tagged
//      atomicMax, warp-aggregated compaction of live edges ----
__device__ __forceinline__ void phaseA(const u64* __restrict__ win,
                                       u64* __restrict__ wout,
                                       int n, int r, int tid0, int nthreads, int lane)
{
    const u64 tag = ((u64)(r + 1)) << 51;
    const int npad = (n + 31) & ~31;          // warp-uniform trips for ballot
    for (int k = tid0; k < npad; k += nthreads) {
        bool live = false; u64 packed = 0;
        if (k < n) {
            u64 w = win[k];
            int e  = (int)(w >> 34);
            int ra = find_c((int)((w >> 17) & 0x1FFFF));
            int rb = find_c((int)(w & 0x1FFFF));
            if (ra != rb) {
                live = true;
                u64 kv = tag | g_key[e];
                atomicMax(&g_best[ra], kv);
                atomicMax(&g_best[rb], kv);
                packed = ((u64)e << 34) | ((u64)ra << 17) | (u64)rb;
            }
        }
        unsigned m = __ballot_sync(0xffffffffu, live);
        if (m) {
            int leader = __ffs(m) - 1;
            int base = 0;
            if (lane == leader) base = atomicAdd(&g_cnt[r], __popc(m));
            base = __shfl_sync(0xffffffffu, base, leader);
            if (live) wout[base + __popc(m & ((1u << lane) - 1))] = packed;
        }
    }
}

__global__ void __launch_bounds__(TPB, 1)
boruvka_kernel(const float* __restrict__ s,
               const float* __restrict__ u,
               const int*   __restrict__ src,
               const int*   __restrict__ dst,
               float*       __restrict__ out)
{
    const int tid  = blockIdx.x * TPB + threadIdx.x;
    const int lane = threadIdx.x & 31;

    // ================= round 0, phase A (fused with init) =================
    // Keys bitwise-match the JAX f32 pipeline (validated rel_err==0.0):
    //   score = 1/(1+expf(-s)) + (-logf(-logf(u+1e-9)+1e-9))
    // Labels are identity at round 0 -> roots are the raw endpoints;
    // g_best/g_cnt are clean at entry (end-of-replay clear protocol).
    {
        const u64 tag0 = 1ULL << 51;
        for (int i = tid; i < NUM_EDGES; i += NT) {   // NUM_EDGES % 32 == 0
            float sp = 1.0f / (1.0f + expf(-s[i]));
            float gb = -logf(-logf(u[i] + 1e-9f) + 1e-9f);
            unsigned ub = __float_as_uint(sp + gb);
            ub = (ub & 0x80000000u) ? ~ub : (ub | 0x80000000u);  // order-preserving
            u64 key = ((u64)ub << 19) | (u64)(524287 - i);       // ties -> lowest idx
            g_key[i] = key;
            out[i] = 0.0f;
            int ra = src[i], rb = dst[i];
            bool live = (ra != rb);
            u64 packed = 0;
            if (live) {
                u64 kv = tag0 | key;
                atomicMax(&g_best[ra], kv);
                atomicMax(&g_best[rb], kv);
                packed = ((u64)i << 34) | ((u64)ra << 17) | (u64)rb;
            }
            unsigned m = __ballot_sync(0xffffffffu, live);
            if (m) {
                int leader = __ffs(m) - 1;
                int base = 0;
                if (lane == leader) base = atomicAdd(&g_cnt[0], __popc(m));
                base = __shfl_sync(0xffffffffu, base, leader);
                if (live) g_wl[0][base + __popc(m & ((1u << lane) - 1))] = packed;
            }
        }
        for (int i = tid; i < NUM_NODES; i += NT) g_label[i] = i;
    }
    gbar();

    // ================= grid rounds =================
    int n = __ldcg(&g_cnt[0]);
    int r = 0;
    while (true) {
        bool fin = (n <= LOCAL_N);
        // ---- phase B: per-edge winner check; hook root -> stored partner ----
        {
            const u64 tag = ((u64)(r + 1)) << 51;
            const u64* wl_ = g_wl[r & 1];
            for (int k = tid; k < n; k += NT) {
                u64 w = wl_[k];
                int e  = (int)(w >> 34);
                int ra = (int)((w >> 17) & 0x1FFFF);
                int rb = (int)(w & 0x1FFFF);
                u64 want = tag | g_key[e];
                bool wa = (__ldcg(&g_best[ra]) == want);
                bool wb = (__ldcg(&g_best[rb]) == want);
                if (wa | wb) {
                    out[e] = 1.0f;
                    if (wa && wb) { if (ra > rb) g_label[ra] = rb; else g_label[rb] = ra; }
                    else if (wa)  g_label[ra] = rb;
                    else          g_label[rb] = ra;
                }
            }
        }
        gbar();
        if (fin) break;
        r++;
        phaseA(g_wl[(r + 1) & 1], g_wl[r & 1], n, r, tid, NT, lane);
        gbar();
        n = __ldcg(&g_cnt[r]);
    }

    // ---- end-of-replay clear (grid part): best + counters back to 0 ----
    for (int i = tid; i < NUM_NODES; i += NT) g_best[i] = 0ULL;
    if (tid < NRND) g_cnt[tid] = 0;
    gbar();
    if (blockIdx.x != 0) return;

    // ================= local mode: block 0 only, n <= LOCAL_N =================
    __shared__ int s_hook;
    int rl = r + 1;
    while (n > 0 && rl < NRND - 1) {
        // A_local (same parity convention: round rl reads wl[(rl+1)&1])
        phaseA(g_wl[(rl + 1) & 1], g_wl[rl & 1], n, rl, threadIdx.x, TPB, lane);
        __syncthreads();
        int nn = __ldcg(&g_cnt[rl]);
        const u64 tagl = ((u64)(rl + 1)) << 51;
        const u64* wo = g_wl[rl & 1];

        // B_local pass 1: read winners into register bitmasks (nn<=8192 -> j<8)
        unsigned maskA = 0, maskB = 0;
        for (int k = threadIdx.x, j = 0; k < nn; k += TPB, j++) {
            u64 w = wo[k];
            int e  = (int)(w >> 34);
            int ra = (int)((w >> 17) & 0x1FFFF);
            int rb = (int)(w & 0x1FFFF);
            u64 want = tagl | g_key[e];
            if (__ldcg(&g_best[ra]) == want) maskA |= 1u << j;
            if (__ldcg(&g_best[rb]) == want) maskB |= 1u << j;
        }
        if (threadIdx.x == 0) s_hook = 0;
        __syncthreads();    // all pass-1 reads complete before any clear

        // B_local pass 2: hook + mark + self-clear touched best slots
        bool hooked = false;
        for (int k = threadIdx.x, j = 0; k < nn; k += TPB, j++) {
            u64 w = wo[k];
            int e  = (int)(w >> 34);
            int ra = (int)((w >> 17) & 0x1FFFF);
            int rb = (int)(w & 0x1FFFF);
            bool wa = (maskA >> j) & 1, wb = (maskB >> j) & 1;
            g_best[ra] = 0ULL;
            g_best[rb] = 0ULL;
            if (wa | wb) {
                out[e] = 1.0f; hooked = true;
                if (wa && wb) { if (ra > rb) g_label[ra] = rb; else g_label[rb] = ra; }
                else if (wa)  g_label[ra] = rb;
                else          g_label[rb] = ra;
            }
        }
        if (hooked) s_hook = 1;
        __syncthreads();
        n = nn;
        if (nn == 0 || !s_hook) break;   // pass-2 clears already done
        rl++;
    }
    // end-of-replay clear (local part): counters used by local rounds
    __syncthreads();
    for (int i = threadIdx.x; i < NRND; i += TPB) g_cnt[i] = 0;
}

extern "C" void kernel_launch(void* const* d_in, const int* in_sizes, int n_in,
                              void* d_out, int out_size)
{
    const float* s   = (const float*)d_in[0];
    const float* u   = (const float*)d_in[1];
    const int*   ei  = (const int*)d_in[2];   // [2, E] row-major
    const int*   src = ei;
    const int*   dst = ei + NUM_EDGES;
    float*       out = (float*)d_out;

    boruvka_kernel<<<BLOCKS, TPB>>>(s, u, src, dst, out);
}